// round 6
// baseline (speedup 1.0000x reference)
#include <cuda_runtime.h>
#include <cuda_bf16.h>
#include <math.h>

// Problem constants (fixed by the dataset)
#define BB 2
#define CC 256
#define HH 200
#define WW 200
#define HWSZ (HH * WW)          // 40000
#define OUT_H 7
#define OUT_W 7
#define GSAMP 2
#define NSAMP (OUT_H * GSAMP * OUT_W * GSAMP)  // 196
#define SPATIAL_SCALE 0.25f

// NHWC scratch: 2*200*200*256 floats = 81.92 MB (static device array: allowed)
__device__ float g_featT[(size_t)BB * HWSZ * CC];

// ---------------------------------------------------------------------------
// Kernel 1: NCHW -> NHWC transpose.
// Per batch, treat as a (C=256) x (HW=40000) matrix transpose -> (HW) x (C).
// Tiled 32x32 via shared memory, fully coalesced both directions.
// ---------------------------------------------------------------------------
__global__ void nchw_to_nhwc_kernel(const float* __restrict__ in) {
    __shared__ float tile[32][33];
    const int b  = blockIdx.z;
    const int p0 = blockIdx.x * 32;   // position (HW) tile origin (1250 tiles)
    const int c0 = blockIdx.y * 32;   // channel tile origin (8 tiles)
    const int tx = threadIdx.x;       // 0..31
    const int ty = threadIdx.y;       // 0..7

    const float* src = in + (size_t)b * CC * HWSZ;
    float* dst = g_featT + (size_t)b * HWSZ * CC;

    #pragma unroll
    for (int i = 0; i < 32; i += 8) {
        // read: consecutive tx -> consecutive p (coalesced)
        tile[ty + i][tx] = src[(size_t)(c0 + ty + i) * HWSZ + (p0 + tx)];
    }
    __syncthreads();
    #pragma unroll
    for (int i = 0; i < 32; i += 8) {
        // write: consecutive tx -> consecutive c (coalesced)
        dst[(size_t)(p0 + ty + i) * CC + (c0 + tx)] = tile[tx][ty + i];
    }
}

// ---------------------------------------------------------------------------
// Kernel 2: RoIAlignRotated gather.
// grid.x = N * 2 : block = (roi n, channel half c0 in {0,128}), 128 threads.
// Phase A: 196 sample points -> 4 corner offsets (pre-multiplied by C) + 4
//          bilinear weights in shared, replicating reference semantics exactly.
// Phase B: each thread owns channel c = c0 + tid; for each of the 49 bins,
//          16 coalesced __ldg gathers from NHWC features; results staged in
//          shared as [c][bin] so the final global store is one contiguous
//          25 KB coalesced block per CTA.
// ---------------------------------------------------------------------------
__global__ __launch_bounds__(128)
void roi_align_rotated_kernel(const float* __restrict__ rois,
                              float* __restrict__ out,
                              int N) {
    __shared__ float s_w1[NSAMP], s_w2[NSAMP], s_w3[NSAMP], s_w4[NSAMP];
    __shared__ int   s_i1[NSAMP], s_i2[NSAMP], s_i3[NSAMP], s_i4[NSAMP];
    __shared__ float s_out[128 * 49];  // 25088 B

    const int n   = blockIdx.x >> 1;
    const int c0  = (blockIdx.x & 1) << 7;   // 0 or 128
    const int tid = threadIdx.x;

    // --- roi params (broadcast load, every thread computes; cheap) ---
    const float* R = rois + (size_t)n * 6;
    const int   b     = (int)R[0];
    const float cx    = R[1] * SPATIAL_SCALE;
    const float cy    = R[2] * SPATIAL_SCALE;
    const float rw    = fmaxf(R[3] * SPATIAL_SCALE, 1.0f);
    const float rh    = fmaxf(R[4] * SPATIAL_SCALE, 1.0f);
    const float theta = R[5];
    const float cost  = cosf(theta);
    const float sint  = sinf(theta);
    const float bin_h = rh * (1.0f / OUT_H);
    const float bin_w = rw * (1.0f / OUT_W);

    // --- Phase A: sample-point precompute ---
    for (int s = tid; s < NSAMP; s += 128) {
        const int r = s / (OUT_W * GSAMP);   // 0..13 (y sample index)
        const int q = s % (OUT_W * GSAMP);   // 0..13 (x sample index)
        const float sy = ((float)r + 0.5f) * (1.0f / GSAMP);
        const float sx = ((float)q + 0.5f) * (1.0f / GSAMP);
        const float yy = -rh * 0.5f + sy * bin_h;
        const float xx = -rw * 0.5f + sx * bin_w;
        const float y = yy * cost - xx * sint + cy;
        const float x = yy * sint + xx * cost + cx;

        const bool inside = (y >= -1.0f) && (y <= (float)HH) &&
                            (x >= -1.0f) && (x <= (float)WW);

        const float yc = fmaxf(y, 0.0f);
        const float xc = fmaxf(x, 0.0f);
        const float fy = floorf(yc);
        const float fx = floorf(xc);
        int yl = min((int)fy, HH - 1);
        int xl = min((int)fx, WW - 1);
        const int yh = min(yl + 1, HH - 1);
        const int xh = min(xl + 1, WW - 1);
        const float ly = (fy >= (float)(HH - 1)) ? 0.0f : (yc - (float)yl);
        const float lx = (fx >= (float)(WW - 1)) ? 0.0f : (xc - (float)xl);
        const float hy = 1.0f - ly;
        const float hx = 1.0f - lx;

        float w1 = hy * hx, w2 = hy * lx, w3 = ly * hx, w4 = ly * lx;
        if (!inside) { w1 = 0.0f; w2 = 0.0f; w3 = 0.0f; w4 = 0.0f; }

        const int base = b * HWSZ;
        s_i1[s] = (base + yl * WW + xl) * CC;
        s_i2[s] = (base + yl * WW + xh) * CC;
        s_i3[s] = (base + yh * WW + xl) * CC;
        s_i4[s] = (base + yh * WW + xh) * CC;
        s_w1[s] = w1; s_w2[s] = w2; s_w3[s] = w3; s_w4[s] = w4;
    }
    __syncthreads();

    // --- Phase B: gather + accumulate ---
    const int c = c0 + tid;
    const float* __restrict__ ft = g_featT;

    #pragma unroll 1
    for (int ph = 0; ph < OUT_H; ph++) {
        #pragma unroll 1
        for (int pw = 0; pw < OUT_W; pw++) {
            float acc = 0.0f;
            #pragma unroll
            for (int iy = 0; iy < GSAMP; iy++) {
                #pragma unroll
                for (int ix = 0; ix < GSAMP; ix++) {
                    const int s = (ph * GSAMP + iy) * (OUT_W * GSAMP)
                                + (pw * GSAMP + ix);
                    acc += s_w1[s] * __ldg(ft + s_i1[s] + c);
                    acc += s_w2[s] * __ldg(ft + s_i2[s] + c);
                    acc += s_w3[s] * __ldg(ft + s_i3[s] + c);
                    acc += s_w4[s] * __ldg(ft + s_i4[s] + c);
                }
            }
            // mean over g*g = 4 samples; stage [c][bin] for coalesced store
            s_out[tid * 49 + ph * OUT_W + pw] = acc * 0.25f;
        }
    }
    __syncthreads();

    // --- Phase C: coalesced contiguous store of this CTA's output slab ---
    float* outp = out + (size_t)n * (CC * 49) + (size_t)c0 * 49;
    #pragma unroll
    for (int i = tid; i < 128 * 49; i += 128) {
        outp[i] = s_out[i];
    }
}

// ---------------------------------------------------------------------------
extern "C" void kernel_launch(void* const* d_in, const int* in_sizes, int n_in,
                              void* d_out, int out_size) {
    // metadata order: features, rois — but disambiguate by size to be safe.
    const float* features;
    const float* rois;
    int rois_elems;
    if (in_sizes[0] > in_sizes[1]) {
        features = (const float*)d_in[0];
        rois     = (const float*)d_in[1];
        rois_elems = in_sizes[1];
    } else {
        features = (const float*)d_in[1];
        rois     = (const float*)d_in[0];
        rois_elems = in_sizes[0];
    }
    const int N = rois_elems / 6;

    // 1) NCHW -> NHWC transpose into device scratch
    dim3 tgrid(HWSZ / 32, CC / 32, BB);   // 1250 x 8 x 2
    dim3 tblk(32, 8);
    nchw_to_nhwc_kernel<<<tgrid, tblk>>>(features);

    // 2) gather kernel: 2 CTAs per roi (channel halves)
    roi_align_rotated_kernel<<<N * 2, 128>>>(rois, (float*)d_out, N);
}

// round 7
// speedup vs baseline: 1.1171x; 1.1171x over previous
#include <cuda_runtime.h>
#include <cuda_bf16.h>
#include <math.h>

// Problem constants (fixed by the dataset)
#define BB 2
#define CC 256
#define HH 200
#define WW 200
#define HWSZ (HH * WW)          // 40000
#define OUT_H 7
#define OUT_W 7
#define GSAMP 2
#define NSAMP (OUT_H * GSAMP * OUT_W * GSAMP)  // 196
#define SPATIAL_SCALE 0.25f
#define NBINS (OUT_H * OUT_W)   // 49
#define RPAD 260                // 256 + 4 : STS.128-aligned (1040B), LDS stride 4 banks

// NHWC scratch: 2*200*200*256 floats = 81.92 MB (static device array: allowed)
__device__ __align__(16) float g_featT[(size_t)BB * HWSZ * CC];

// ---------------------------------------------------------------------------
// Kernel 1: NCHW -> NHWC transpose (tiled 32x32, coalesced both sides).
// ---------------------------------------------------------------------------
__global__ void nchw_to_nhwc_kernel(const float* __restrict__ in) {
    __shared__ float tile[32][33];
    const int b  = blockIdx.z;
    const int p0 = blockIdx.x * 32;
    const int c0 = blockIdx.y * 32;
    const int tx = threadIdx.x;
    const int ty = threadIdx.y;

    const float* src = in + (size_t)b * CC * HWSZ;
    float* dst = g_featT + (size_t)b * HWSZ * CC;

    #pragma unroll
    for (int i = 0; i < 32; i += 8)
        tile[ty + i][tx] = src[(size_t)(c0 + ty + i) * HWSZ + (p0 + tx)];
    __syncthreads();
    #pragma unroll
    for (int i = 0; i < 32; i += 8)
        dst[(size_t)(p0 + ty + i) * CC + (c0 + tx)] = tile[tx][ty + i];
}

// ---------------------------------------------------------------------------
// Kernel 2: RoIAlignRotated gather, float4-vectorized.
// grid = N (one CTA per roi), block = 256.
// Thread t: channel-quad c4 = t & 63 (channels 4*c4 .. 4*c4+3),
//           bin group bg = t >> 6, handles bins j = bg, bg+4, ... < 49.
// Phase A: precompute 196 sample points: 4 corner float4-indices + 4 weights.
// Phase B: per bin, 16 x LDG.128 gathers (coalesced: warp = consecutive c4),
//          accumulate float4, STS.128 into bin-major padded staging buffer.
// Phase C: coalesced contiguous 50KB global store of the roi's output slab.
// ---------------------------------------------------------------------------
__global__ __launch_bounds__(256)
void roi_align_rotated_kernel(const float* __restrict__ rois,
                              float* __restrict__ out,
                              int N) {
    __shared__ float s_w[NSAMP][4];
    __shared__ int   s_i[NSAMP][4];          // float4-element indices
    __shared__ float s_out[NBINS * RPAD];    // 50960 B

    const int n   = blockIdx.x;
    const int tid = threadIdx.x;
    const int c4  = tid & 63;
    const int bg  = tid >> 6;

    // --- roi params (broadcast) ---
    const float* R = rois + (size_t)n * 6;
    const int   b     = (int)R[0];
    const float cx    = R[1] * SPATIAL_SCALE;
    const float cy    = R[2] * SPATIAL_SCALE;
    const float rw    = fmaxf(R[3] * SPATIAL_SCALE, 1.0f);
    const float rh    = fmaxf(R[4] * SPATIAL_SCALE, 1.0f);
    const float theta = R[5];
    const float cost  = cosf(theta);
    const float sint  = sinf(theta);
    const float bin_h = rh * (1.0f / OUT_H);
    const float bin_w = rw * (1.0f / OUT_W);

    // --- Phase A: sample-point precompute (reference semantics exactly) ---
    if (tid < NSAMP) {
        const int s = tid;
        const int r = s / (OUT_W * GSAMP);
        const int q = s % (OUT_W * GSAMP);
        const float sy = ((float)r + 0.5f) * (1.0f / GSAMP);
        const float sx = ((float)q + 0.5f) * (1.0f / GSAMP);
        const float yy = -rh * 0.5f + sy * bin_h;
        const float xx = -rw * 0.5f + sx * bin_w;
        const float y = yy * cost - xx * sint + cy;
        const float x = yy * sint + xx * cost + cx;

        const bool inside = (y >= -1.0f) && (y <= (float)HH) &&
                            (x >= -1.0f) && (x <= (float)WW);

        const float yc = fmaxf(y, 0.0f);
        const float xc = fmaxf(x, 0.0f);
        const float fy = floorf(yc);
        const float fx = floorf(xc);
        int yl = min((int)fy, HH - 1);
        int xl = min((int)fx, WW - 1);
        const int yh = min(yl + 1, HH - 1);
        const int xh = min(xl + 1, WW - 1);
        const float ly = (fy >= (float)(HH - 1)) ? 0.0f : (yc - (float)yl);
        const float lx = (fx >= (float)(WW - 1)) ? 0.0f : (xc - (float)xl);
        const float hy = 1.0f - ly;
        const float hx = 1.0f - lx;

        float w1 = hy * hx, w2 = hy * lx, w3 = ly * hx, w4 = ly * lx;
        if (!inside) { w1 = 0.0f; w2 = 0.0f; w3 = 0.0f; w4 = 0.0f; }

        // index in float4 units: (pos)*CC/4 = pos*64
        const int base = b * HWSZ;
        s_i[s][0] = (base + yl * WW + xl) * (CC / 4);
        s_i[s][1] = (base + yl * WW + xh) * (CC / 4);
        s_i[s][2] = (base + yh * WW + xl) * (CC / 4);
        s_i[s][3] = (base + yh * WW + xh) * (CC / 4);
        s_w[s][0] = w1; s_w[s][1] = w2; s_w[s][2] = w3; s_w[s][3] = w4;
    }
    __syncthreads();

    // --- Phase B: float4 gather + accumulate ---
    const float4* __restrict__ ft4 =
        reinterpret_cast<const float4*>(g_featT) + c4;

    #pragma unroll 1
    for (int j = bg; j < NBINS; j += 4) {
        const int ph = j / OUT_W;
        const int pw = j - ph * OUT_W;
        float ax = 0.0f, ay = 0.0f, az = 0.0f, aw = 0.0f;
        #pragma unroll
        for (int iy = 0; iy < GSAMP; iy++) {
            #pragma unroll
            for (int ix = 0; ix < GSAMP; ix++) {
                const int s = (ph * GSAMP + iy) * (OUT_W * GSAMP)
                            + (pw * GSAMP + ix);
                #pragma unroll
                for (int k = 0; k < 4; k++) {
                    const float w  = s_w[s][k];
                    const float4 v = __ldg(ft4 + s_i[s][k]);
                    ax += w * v.x; ay += w * v.y;
                    az += w * v.z; aw += w * v.w;
                }
            }
        }
        // mean over 2x2 samples; stage bin-major [j][c] (conflict-free STS.128)
        float4 res = make_float4(ax * 0.25f, ay * 0.25f, az * 0.25f, aw * 0.25f);
        *reinterpret_cast<float4*>(&s_out[j * RPAD + 4 * c4]) = res;
    }
    __syncthreads();

    // --- Phase C: coalesced contiguous store of this roi's output slab ---
    float* outp = out + (size_t)n * (CC * NBINS);
    #pragma unroll 1
    for (int i = tid; i < CC * NBINS; i += 256) {
        const int c = i / NBINS;
        const int j = i - c * NBINS;
        outp[i] = s_out[j * RPAD + c];
    }
}

// ---------------------------------------------------------------------------
extern "C" void kernel_launch(void* const* d_in, const int* in_sizes, int n_in,
                              void* d_out, int out_size) {
    const float* features;
    const float* rois;
    int rois_elems;
    if (in_sizes[0] > in_sizes[1]) {
        features = (const float*)d_in[0];
        rois     = (const float*)d_in[1];
        rois_elems = in_sizes[1];
    } else {
        features = (const float*)d_in[1];
        rois     = (const float*)d_in[0];
        rois_elems = in_sizes[0];
    }
    const int N = rois_elems / 6;

    dim3 tgrid(HWSZ / 32, CC / 32, BB);
    dim3 tblk(32, 8);
    nchw_to_nhwc_kernel<<<tgrid, tblk>>>(features);

    roi_align_rotated_kernel<<<N, 256>>>(rois, (float*)d_out, N);
}

// round 8
// speedup vs baseline: 1.3233x; 1.1846x over previous
#include <cuda_runtime.h>
#include <cuda_bf16.h>
#include <math.h>

// Problem constants (fixed by the dataset)
#define BB 2
#define CC 256
#define HH 200
#define WW 200
#define HWSZ (HH * WW)          // 40000
#define OUT_H 7
#define OUT_W 7
#define GSAMP 2
#define NSAMP (OUT_H * GSAMP * OUT_W * GSAMP)  // 196
#define SPATIAL_SCALE 0.25f
#define NBINS (OUT_H * OUT_W)   // 49
#define HALF_C 128              // channels per CTA
#define RPITCH 132              // 128 + 4 floats; 528B rows (16B aligned)

// NHWC scratch: 2*200*200*256 floats = 81.92 MB (static device array: allowed)
__device__ __align__(16) float g_featT[(size_t)BB * HWSZ * CC];

// ---------------------------------------------------------------------------
// Kernel 1: NCHW -> NHWC transpose (tiled 32x32, coalesced both sides).
// ---------------------------------------------------------------------------
__global__ void nchw_to_nhwc_kernel(const float* __restrict__ in) {
    __shared__ float tile[32][33];
    const int b  = blockIdx.z;
    const int p0 = blockIdx.x * 32;
    const int c0 = blockIdx.y * 32;
    const int tx = threadIdx.x;
    const int ty = threadIdx.y;

    const float* src = in + (size_t)b * CC * HWSZ;
    float* dst = g_featT + (size_t)b * HWSZ * CC;

    #pragma unroll
    for (int i = 0; i < 32; i += 8)
        tile[ty + i][tx] = src[(size_t)(c0 + ty + i) * HWSZ + (p0 + tx)];
    __syncthreads();
    #pragma unroll
    for (int i = 0; i < 32; i += 8)
        dst[(size_t)(p0 + ty + i) * CC + (c0 + tx)] = tile[tx][ty + i];
}

// ---------------------------------------------------------------------------
// Kernel 2: RoIAlignRotated gather, float4-vectorized, 2 CTAs per roi.
// grid = 2N. CTA handles 128 channels (half = blockIdx.x & 1).
// Thread t: channel-quad q = t & 31 (local channels 4q..4q+3),
//           bin group bg = t >> 5 (bins j = bg, bg+8, ... < 49).
// smem ~32KB + regs forced <=42  ->  6 CTAs/SM = 48 warps (75% occ).
// ---------------------------------------------------------------------------
__global__ __launch_bounds__(256, 6)
void roi_align_rotated_kernel(const float* __restrict__ rois,
                              float* __restrict__ out,
                              int N) {
    __shared__ float4 s_w[NSAMP];
    __shared__ int4   s_i[NSAMP];            // float4-element indices
    __shared__ float  s_out[NBINS * RPITCH]; // 25872 B

    const int n    = blockIdx.x >> 1;
    const int half = blockIdx.x & 1;
    const int tid  = threadIdx.x;
    const int q    = tid & 31;                // local channel-quad 0..31
    const int bg   = tid >> 5;                // 0..7

    // --- roi params (broadcast) ---
    const float* R = rois + (size_t)n * 6;
    const int   b     = (int)R[0];
    const float cx    = R[1] * SPATIAL_SCALE;
    const float cy    = R[2] * SPATIAL_SCALE;
    const float rw    = fmaxf(R[3] * SPATIAL_SCALE, 1.0f);
    const float rh    = fmaxf(R[4] * SPATIAL_SCALE, 1.0f);
    const float theta = R[5];
    const float cost  = cosf(theta);
    const float sint  = sinf(theta);
    const float bin_h = rh * (1.0f / OUT_H);
    const float bin_w = rw * (1.0f / OUT_W);

    // --- Phase A: sample-point precompute (reference semantics exactly) ---
    if (tid < NSAMP) {
        const int s = tid;
        const int r = s / (OUT_W * GSAMP);
        const int p = s % (OUT_W * GSAMP);
        const float sy = ((float)r + 0.5f) * (1.0f / GSAMP);
        const float sx = ((float)p + 0.5f) * (1.0f / GSAMP);
        const float yy = -rh * 0.5f + sy * bin_h;
        const float xx = -rw * 0.5f + sx * bin_w;
        const float y = yy * cost - xx * sint + cy;
        const float x = yy * sint + xx * cost + cx;

        const bool inside = (y >= -1.0f) && (y <= (float)HH) &&
                            (x >= -1.0f) && (x <= (float)WW);

        const float yc = fmaxf(y, 0.0f);
        const float xc = fmaxf(x, 0.0f);
        const float fy = floorf(yc);
        const float fx = floorf(xc);
        int yl = min((int)fy, HH - 1);
        int xl = min((int)fx, WW - 1);
        const int yh = min(yl + 1, HH - 1);
        const int xh = min(xl + 1, WW - 1);
        const float ly = (fy >= (float)(HH - 1)) ? 0.0f : (yc - (float)yl);
        const float lx = (fx >= (float)(WW - 1)) ? 0.0f : (xc - (float)xl);
        const float hy = 1.0f - ly;
        const float hx = 1.0f - lx;

        float4 w = make_float4(hy * hx, hy * lx, ly * hx, ly * lx);
        if (!inside) w = make_float4(0.f, 0.f, 0.f, 0.f);

        const int base = b * HWSZ;
        int4 idx;
        idx.x = (base + yl * WW + xl) * (CC / 4);
        idx.y = (base + yl * WW + xh) * (CC / 4);
        idx.z = (base + yh * WW + xl) * (CC / 4);
        idx.w = (base + yh * WW + xh) * (CC / 4);
        s_i[s] = idx;
        s_w[s] = w;
    }
    __syncthreads();

    // --- Phase B: float4 gather + accumulate ---
    // global channel-quad for this thread:
    const float4* __restrict__ ft4 =
        reinterpret_cast<const float4*>(g_featT) + (half * 32 + q);

    #pragma unroll 1
    for (int j = bg; j < NBINS; j += 8) {
        const int ph = j / OUT_W;
        const int pw = j - ph * OUT_W;
        float ax = 0.0f, ay = 0.0f, az = 0.0f, aw = 0.0f;
        #pragma unroll
        for (int iy = 0; iy < GSAMP; iy++) {
            #pragma unroll
            for (int ix = 0; ix < GSAMP; ix++) {
                const int s = (ph * GSAMP + iy) * (OUT_W * GSAMP)
                            + (pw * GSAMP + ix);
                const int4   ii = s_i[s];   // LDS.128 broadcast
                const float4 wv = s_w[s];   // LDS.128 broadcast
                const float4 v1 = __ldg(ft4 + ii.x);
                const float4 v2 = __ldg(ft4 + ii.y);
                const float4 v3 = __ldg(ft4 + ii.z);
                const float4 v4 = __ldg(ft4 + ii.w);
                ax += wv.x * v1.x + wv.y * v2.x + wv.z * v3.x + wv.w * v4.x;
                ay += wv.x * v1.y + wv.y * v2.y + wv.z * v3.y + wv.w * v4.y;
                az += wv.x * v1.z + wv.y * v2.z + wv.z * v3.z + wv.w * v4.z;
                aw += wv.x * v1.w + wv.y * v2.w + wv.z * v3.w + wv.w * v4.w;
            }
        }
        float4 res = make_float4(ax * 0.25f, ay * 0.25f, az * 0.25f, aw * 0.25f);
        // bin-major staging; lanes of a warp -> contiguous 512B (STS.128, no conflict)
        *reinterpret_cast<float4*>(&s_out[j * RPITCH + 4 * q]) = res;
    }
    __syncthreads();

    // --- Phase C: coalesced contiguous store of this half's output slab ---
    float* outp = out + (size_t)n * (CC * NBINS) + (size_t)half * (HALF_C * NBINS);
    #pragma unroll 1
    for (int i = tid; i < HALF_C * NBINS; i += 256) {
        const int c = i / NBINS;      // local channel 0..127
        const int j = i - c * NBINS;  // bin 0..48
        outp[i] = s_out[j * RPITCH + c];
    }
}

// ---------------------------------------------------------------------------
extern "C" void kernel_launch(void* const* d_in, const int* in_sizes, int n_in,
                              void* d_out, int out_size) {
    const float* features;
    const float* rois;
    int rois_elems;
    if (in_sizes[0] > in_sizes[1]) {
        features = (const float*)d_in[0];
        rois     = (const float*)d_in[1];
        rois_elems = in_sizes[1];
    } else {
        features = (const float*)d_in[1];
        rois     = (const float*)d_in[0];
        rois_elems = in_sizes[0];
    }
    const int N = rois_elems / 6;

    dim3 tgrid(HWSZ / 32, CC / 32, BB);
    dim3 tblk(32, 8);
    nchw_to_nhwc_kernel<<<tgrid, tblk>>>(features);

    roi_align_rotated_kernel<<<N * 2, 256>>>(rois, (float*)d_out, N);
}

// round 9
// speedup vs baseline: 1.6818x; 1.2709x over previous
#include <cuda_runtime.h>
#include <cuda_fp16.h>
#include <cuda_bf16.h>
#include <math.h>

// Problem constants (fixed by the dataset)
#define BB 2
#define CC 256
#define HH 200
#define WW 200
#define HWSZ (HH * WW)          // 40000
#define OUT_H 7
#define OUT_W 7
#define GSAMP 2
#define NSAMP (OUT_H * GSAMP * OUT_W * GSAMP)  // 196
#define SPATIAL_SCALE 0.25f
#define NBINS (OUT_H * OUT_W)   // 49
#define HALF_C 128              // channels per CTA
#define RPITCH 132              // 128 + 4 floats per staging row

// NHWC fp16 scratch: 2*200*200*256 halves = 40.96 MB (static device array: allowed)
__device__ __align__(16) __half g_featT[(size_t)BB * HWSZ * CC];

// ---------------------------------------------------------------------------
// Kernel 1: NCHW fp32 -> NHWC fp16 transpose (tiled 32x32, coalesced, half2
// vectorized stores).
// ---------------------------------------------------------------------------
__global__ void nchw_to_nhwc_half_kernel(const float* __restrict__ in) {
    __shared__ float tile[32][33];
    const int b  = blockIdx.z;
    const int p0 = blockIdx.x * 32;   // spatial tile origin
    const int c0 = blockIdx.y * 32;   // channel tile origin
    const int tx = threadIdx.x;       // 0..31
    const int ty = threadIdx.y;       // 0..7
    const int tid = ty * 32 + tx;

    const float* src = in + (size_t)b * CC * HWSZ;
    __half* dst = g_featT + (size_t)b * HWSZ * CC;

    #pragma unroll
    for (int i = 0; i < 32; i += 8)
        tile[ty + i][tx] = src[(size_t)(c0 + ty + i) * HWSZ + (p0 + tx)];
    __syncthreads();

    // 32 positions x 16 half2 = 512 half2 per tile; 256 threads, 2 iterations.
    #pragma unroll
    for (int it = 0; it < 2; it++) {
        const int e  = it * 256 + tid;
        const int pl = e >> 4;        // local position 0..31
        const int h  = e & 15;        // half2 index within 32 channels
        const float f0 = tile[2 * h][pl];
        const float f1 = tile[2 * h + 1][pl];
        __half2 v = __floats2half2_rn(f0, f1);
        *reinterpret_cast<__half2*>(dst + (size_t)(p0 + pl) * CC + c0 + 2 * h) = v;
    }
}

// ---------------------------------------------------------------------------
// Kernel 2: RoIAlignRotated gather, fp16 features, 8-channel octs.
// grid = 2N (channel halves). 256 threads.
// Thread t: oct q = t & 15 (8 local channels 8q..8q+7),
//           bin group bg = t >> 4, bins j = bg, bg+16, ... < 49.
// Each LDG.128 fetches 8 fp16 channels; fp32 accumulation.
// ---------------------------------------------------------------------------
__global__ __launch_bounds__(256, 6)
void roi_align_rotated_kernel(const float* __restrict__ rois,
                              float* __restrict__ out,
                              int N) {
    __shared__ float4 s_w[NSAMP];
    __shared__ int4   s_i[NSAMP];            // oct (8-half / 16B) indices
    __shared__ float  s_out[NBINS * RPITCH]; // 25872 B

    const int n    = blockIdx.x >> 1;
    const int half = blockIdx.x & 1;
    const int tid  = threadIdx.x;
    const int q    = tid & 15;                // local oct 0..15
    const int bg   = tid >> 4;                // 0..15

    // --- roi params (broadcast) ---
    const float* R = rois + (size_t)n * 6;
    const int   b     = (int)R[0];
    const float cx    = R[1] * SPATIAL_SCALE;
    const float cy    = R[2] * SPATIAL_SCALE;
    const float rw    = fmaxf(R[3] * SPATIAL_SCALE, 1.0f);
    const float rh    = fmaxf(R[4] * SPATIAL_SCALE, 1.0f);
    const float theta = R[5];
    const float cost  = cosf(theta);
    const float sint  = sinf(theta);
    const float bin_h = rh * (1.0f / OUT_H);
    const float bin_w = rw * (1.0f / OUT_W);

    // --- Phase A: sample-point precompute (reference semantics exactly) ---
    if (tid < NSAMP) {
        const int s = tid;
        const int r = s / (OUT_W * GSAMP);
        const int p = s % (OUT_W * GSAMP);
        const float sy = ((float)r + 0.5f) * (1.0f / GSAMP);
        const float sx = ((float)p + 0.5f) * (1.0f / GSAMP);
        const float yy = -rh * 0.5f + sy * bin_h;
        const float xx = -rw * 0.5f + sx * bin_w;
        const float y = yy * cost - xx * sint + cy;
        const float x = yy * sint + xx * cost + cx;

        const bool inside = (y >= -1.0f) && (y <= (float)HH) &&
                            (x >= -1.0f) && (x <= (float)WW);

        const float yc = fmaxf(y, 0.0f);
        const float xc = fmaxf(x, 0.0f);
        const float fy = floorf(yc);
        const float fx = floorf(xc);
        int yl = min((int)fy, HH - 1);
        int xl = min((int)fx, WW - 1);
        const int yh = min(yl + 1, HH - 1);
        const int xh = min(xl + 1, WW - 1);
        const float ly = (fy >= (float)(HH - 1)) ? 0.0f : (yc - (float)yl);
        const float lx = (fx >= (float)(WW - 1)) ? 0.0f : (xc - (float)xl);
        const float hy = 1.0f - ly;
        const float hx = 1.0f - lx;

        float4 w = make_float4(hy * hx, hy * lx, ly * hx, ly * lx);
        if (!inside) w = make_float4(0.f, 0.f, 0.f, 0.f);

        // index in oct (16B) units: pos * (CC/8) = pos * 32
        const int base = b * HWSZ;
        int4 idx;
        idx.x = (base + yl * WW + xl) * (CC / 8);
        idx.y = (base + yl * WW + xh) * (CC / 8);
        idx.z = (base + yh * WW + xl) * (CC / 8);
        idx.w = (base + yh * WW + xh) * (CC / 8);
        s_i[s] = idx;
        s_w[s] = w;
    }
    __syncthreads();

    // --- Phase B: fp16 oct gather + fp32 accumulate ---
    const uint4* __restrict__ ft8 =
        reinterpret_cast<const uint4*>(g_featT) + (half * 16 + q);

    #pragma unroll 1
    for (int j = bg; j < NBINS; j += 16) {
        const int ph = j / OUT_W;
        const int pw = j - ph * OUT_W;
        float acc[8];
        #pragma unroll
        for (int k = 0; k < 8; k++) acc[k] = 0.0f;

        #pragma unroll
        for (int iy = 0; iy < GSAMP; iy++) {
            #pragma unroll
            for (int ix = 0; ix < GSAMP; ix++) {
                const int s = (ph * GSAMP + iy) * (OUT_W * GSAMP)
                            + (pw * GSAMP + ix);
                const int4   ii = s_i[s];   // LDS.128 broadcast
                const float4 wv = s_w[s];   // LDS.128 broadcast
                const uint4 u1 = __ldg(ft8 + ii.x);
                const uint4 u2 = __ldg(ft8 + ii.y);
                const uint4 u3 = __ldg(ft8 + ii.z);
                const uint4 u4 = __ldg(ft8 + ii.w);
                const __half2* h1 = reinterpret_cast<const __half2*>(&u1);
                const __half2* h2 = reinterpret_cast<const __half2*>(&u2);
                const __half2* h3 = reinterpret_cast<const __half2*>(&u3);
                const __half2* h4 = reinterpret_cast<const __half2*>(&u4);
                #pragma unroll
                for (int k = 0; k < 4; k++) {
                    const float2 f1 = __half22float2(h1[k]);
                    const float2 f2 = __half22float2(h2[k]);
                    const float2 f3 = __half22float2(h3[k]);
                    const float2 f4 = __half22float2(h4[k]);
                    acc[2*k]   += wv.x * f1.x + wv.y * f2.x
                                + wv.z * f3.x + wv.w * f4.x;
                    acc[2*k+1] += wv.x * f1.y + wv.y * f2.y
                                + wv.z * f3.y + wv.w * f4.y;
                }
            }
        }
        // mean over 2x2 samples; stage bin-major (two STS.128, conflict-free)
        float4 r0 = make_float4(acc[0] * 0.25f, acc[1] * 0.25f,
                                acc[2] * 0.25f, acc[3] * 0.25f);
        float4 r1 = make_float4(acc[4] * 0.25f, acc[5] * 0.25f,
                                acc[6] * 0.25f, acc[7] * 0.25f);
        float* row = &s_out[j * RPITCH + 8 * q];
        *reinterpret_cast<float4*>(row)     = r0;
        *reinterpret_cast<float4*>(row + 4) = r1;
    }
    __syncthreads();

    // --- Phase C: coalesced contiguous store of this half's output slab ---
    float* outp = out + (size_t)n * (CC * NBINS) + (size_t)half * (HALF_C * NBINS);
    #pragma unroll 1
    for (int i = tid; i < HALF_C * NBINS; i += 256) {
        const int c = i / NBINS;      // local channel 0..127
        const int j = i - c * NBINS;  // bin 0..48
        outp[i] = s_out[j * RPITCH + c];
    }
}

// ---------------------------------------------------------------------------
extern "C" void kernel_launch(void* const* d_in, const int* in_sizes, int n_in,
                              void* d_out, int out_size) {
    const float* features;
    const float* rois;
    int rois_elems;
    if (in_sizes[0] > in_sizes[1]) {
        features = (const float*)d_in[0];
        rois     = (const float*)d_in[1];
        rois_elems = in_sizes[1];
    } else {
        features = (const float*)d_in[1];
        rois     = (const float*)d_in[0];
        rois_elems = in_sizes[0];
    }
    const int N = rois_elems / 6;

    dim3 tgrid(HWSZ / 32, CC / 32, BB);
    dim3 tblk(32, 8);
    nchw_to_nhwc_half_kernel<<<tgrid, tblk>>>(features);

    roi_align_rotated_kernel<<<N * 2, 256>>>(rois, (float*)d_out, N);
}

// round 10
// speedup vs baseline: 1.7278x; 1.0274x over previous
#include <cuda_runtime.h>
#include <cuda_fp16.h>
#include <cuda_bf16.h>
#include <math.h>

// Problem constants (fixed by the dataset)
#define BB 2
#define CC 256
#define HH 200
#define WW 200
#define HWSZ (HH * WW)          // 40000
#define OUT_H 7
#define OUT_W 7
#define GSAMP 2
#define NSAMP (OUT_H * GSAMP * OUT_W * GSAMP)  // 196
#define SPATIAL_SCALE 0.25f
#define NBINS (OUT_H * OUT_W)   // 49
#define HALF_C 128              // channels per CTA
#define RPITCH 132              // 128 + 4 floats per staging row

// NHWC fp16 scratch: 2*200*200*256 halves = 40.96 MB (static device array: allowed)
__device__ __align__(16) __half g_featT[(size_t)BB * HWSZ * CC];

__device__ __forceinline__ __half2 u2h(unsigned int u) {
    __half2 h; *reinterpret_cast<unsigned int*>(&h) = u; return h;
}
__device__ __forceinline__ unsigned int h2u(__half2 h) {
    return *reinterpret_cast<unsigned int*>(&h);
}

// ---------------------------------------------------------------------------
// Kernel 1: NCHW fp32 -> NHWC fp16 transpose (tiled 32x32, coalesced, half2
// vectorized stores). DRAM-bound at ~123MB total traffic.
// ---------------------------------------------------------------------------
__global__ void nchw_to_nhwc_half_kernel(const float* __restrict__ in) {
    __shared__ float tile[32][33];
    const int b  = blockIdx.z;
    const int p0 = blockIdx.x * 32;   // spatial tile origin
    const int c0 = blockIdx.y * 32;   // channel tile origin
    const int tx = threadIdx.x;       // 0..31
    const int ty = threadIdx.y;       // 0..7
    const int tid = ty * 32 + tx;

    const float* src = in + (size_t)b * CC * HWSZ;
    __half* dst = g_featT + (size_t)b * HWSZ * CC;

    #pragma unroll
    for (int i = 0; i < 32; i += 8)
        tile[ty + i][tx] = src[(size_t)(c0 + ty + i) * HWSZ + (p0 + tx)];
    __syncthreads();

    #pragma unroll
    for (int it = 0; it < 2; it++) {
        const int e  = it * 256 + tid;
        const int pl = e >> 4;        // local position 0..31
        const int h  = e & 15;        // half2 index within 32 channels
        const float f0 = tile[2 * h][pl];
        const float f1 = tile[2 * h + 1][pl];
        __half2 v = __floats2half2_rn(f0, f1);
        *reinterpret_cast<__half2*>(dst + (size_t)(p0 + pl) * CC + c0 + 2 * h) = v;
    }
}

// ---------------------------------------------------------------------------
// Kernel 2: RoIAlignRotated gather, fp16 features + half2 bilinear math.
// grid = 2N (channel halves). 256 threads.
// Thread t: oct q = t & 15 (8 local channels), bin group bg = t >> 4.
// Per sample: 4-corner bilinear combo in half2 (HMUL2 + 3x HFMA2 per slot),
// one convert per slot, fp32 accumulation across the 2x2 samples.
// ---------------------------------------------------------------------------
__global__ __launch_bounds__(256, 6)
void roi_align_rotated_kernel(const float* __restrict__ rois,
                              float* __restrict__ out,
                              int N) {
    __shared__ uint4 s_wh[NSAMP];            // 4 duplicated-half2 weights
    __shared__ int4  s_i[NSAMP];             // oct (16B) indices
    __shared__ float s_out[NBINS * RPITCH];  // 25872 B

    const int n    = blockIdx.x >> 1;
    const int half = blockIdx.x & 1;
    const int tid  = threadIdx.x;
    const int q    = tid & 15;                // local oct 0..15
    const int bg   = tid >> 4;                // 0..15

    // --- roi params (broadcast) ---
    const float* R = rois + (size_t)n * 6;
    const int   b     = (int)R[0];
    const float cx    = R[1] * SPATIAL_SCALE;
    const float cy    = R[2] * SPATIAL_SCALE;
    const float rw    = fmaxf(R[3] * SPATIAL_SCALE, 1.0f);
    const float rh    = fmaxf(R[4] * SPATIAL_SCALE, 1.0f);
    const float theta = R[5];
    const float cost  = cosf(theta);
    const float sint  = sinf(theta);
    const float bin_h = rh * (1.0f / OUT_H);
    const float bin_w = rw * (1.0f / OUT_W);

    // --- Phase A: sample-point precompute (reference semantics exactly) ---
    if (tid < NSAMP) {
        const int s = tid;
        const int r = s / (OUT_W * GSAMP);
        const int p = s % (OUT_W * GSAMP);
        const float sy = ((float)r + 0.5f) * (1.0f / GSAMP);
        const float sx = ((float)p + 0.5f) * (1.0f / GSAMP);
        const float yy = -rh * 0.5f + sy * bin_h;
        const float xx = -rw * 0.5f + sx * bin_w;
        const float y = yy * cost - xx * sint + cy;
        const float x = yy * sint + xx * cost + cx;

        const bool inside = (y >= -1.0f) && (y <= (float)HH) &&
                            (x >= -1.0f) && (x <= (float)WW);

        const float yc = fmaxf(y, 0.0f);
        const float xc = fmaxf(x, 0.0f);
        const float fy = floorf(yc);
        const float fx = floorf(xc);
        int yl = min((int)fy, HH - 1);
        int xl = min((int)fx, WW - 1);
        const int yh = min(yl + 1, HH - 1);
        const int xh = min(xl + 1, WW - 1);
        const float ly = (fy >= (float)(HH - 1)) ? 0.0f : (yc - (float)yl);
        const float lx = (fx >= (float)(WW - 1)) ? 0.0f : (xc - (float)xl);
        const float hy = 1.0f - ly;
        const float hx = 1.0f - lx;

        float w1 = hy * hx, w2 = hy * lx, w3 = ly * hx, w4 = ly * lx;
        if (!inside) { w1 = 0.f; w2 = 0.f; w3 = 0.f; w4 = 0.f; }

        uint4 wh;
        wh.x = h2u(__float2half2_rn(w1));   // (w1, w1)
        wh.y = h2u(__float2half2_rn(w2));
        wh.z = h2u(__float2half2_rn(w3));
        wh.w = h2u(__float2half2_rn(w4));

        // index in oct (16B) units: pos * (CC/8) = pos * 32
        const int base = b * HWSZ;
        int4 idx;
        idx.x = (base + yl * WW + xl) * (CC / 8);
        idx.y = (base + yl * WW + xh) * (CC / 8);
        idx.z = (base + yh * WW + xl) * (CC / 8);
        idx.w = (base + yh * WW + xh) * (CC / 8);
        s_i[s]  = idx;
        s_wh[s] = wh;
    }
    __syncthreads();

    // --- Phase B: fp16 oct gather, half2 bilinear, fp32 cross-sample acc ---
    const uint4* __restrict__ ft8 =
        reinterpret_cast<const uint4*>(g_featT) + (half * 16 + q);

    #pragma unroll 1
    for (int j = bg; j < NBINS; j += 16) {
        const int ph = j / OUT_W;
        const int pw = j - ph * OUT_W;
        float acc[8];
        #pragma unroll
        for (int k = 0; k < 8; k++) acc[k] = 0.0f;

        #pragma unroll
        for (int iy = 0; iy < GSAMP; iy++) {
            #pragma unroll
            for (int ix = 0; ix < GSAMP; ix++) {
                const int s = (ph * GSAMP + iy) * (OUT_W * GSAMP)
                            + (pw * GSAMP + ix);
                const int4  ii = s_i[s];    // LDS.128 broadcast
                const uint4 wh = s_wh[s];   // LDS.128 broadcast
                const __half2 w1 = u2h(wh.x);
                const __half2 w2 = u2h(wh.y);
                const __half2 w3 = u2h(wh.z);
                const __half2 w4 = u2h(wh.w);
                const uint4 u1 = __ldg(ft8 + ii.x);
                const uint4 u2 = __ldg(ft8 + ii.y);
                const uint4 u3 = __ldg(ft8 + ii.z);
                const uint4 u4 = __ldg(ft8 + ii.w);
                const __half2* h1 = reinterpret_cast<const __half2*>(&u1);
                const __half2* h2 = reinterpret_cast<const __half2*>(&u2);
                const __half2* h3 = reinterpret_cast<const __half2*>(&u3);
                const __half2* h4 = reinterpret_cast<const __half2*>(&u4);
                #pragma unroll
                for (int k = 0; k < 4; k++) {
                    __half2 t = __hmul2(h1[k], w1);
                    t = __hfma2(h2[k], w2, t);
                    t = __hfma2(h3[k], w3, t);
                    t = __hfma2(h4[k], w4, t);
                    const float2 f = __half22float2(t);
                    acc[2*k]   += f.x;
                    acc[2*k+1] += f.y;
                }
            }
        }
        // mean over 2x2 samples; stage bin-major (two STS.128, conflict-free)
        float4 r0 = make_float4(acc[0] * 0.25f, acc[1] * 0.25f,
                                acc[2] * 0.25f, acc[3] * 0.25f);
        float4 r1 = make_float4(acc[4] * 0.25f, acc[5] * 0.25f,
                                acc[6] * 0.25f, acc[7] * 0.25f);
        float* row = &s_out[j * RPITCH + 8 * q];
        *reinterpret_cast<float4*>(row)     = r0;
        *reinterpret_cast<float4*>(row + 4) = r1;
    }
    __syncthreads();

    // --- Phase C: coalesced contiguous store of this half's output slab ---
    float* outp = out + (size_t)n * (CC * NBINS) + (size_t)half * (HALF_C * NBINS);
    #pragma unroll 1
    for (int i = tid; i < HALF_C * NBINS; i += 256) {
        const int c = i / NBINS;      // local channel 0..127
        const int j = i - c * NBINS;  // bin 0..48
        outp[i] = s_out[j * RPITCH + c];
    }
}

// ---------------------------------------------------------------------------
extern "C" void kernel_launch(void* const* d_in, const int* in_sizes, int n_in,
                              void* d_out, int out_size) {
    const float* features;
    const float* rois;
    int rois_elems;
    if (in_sizes[0] > in_sizes[1]) {
        features = (const float*)d_in[0];
        rois     = (const float*)d_in[1];
        rois_elems = in_sizes[1];
    } else {
        features = (const float*)d_in[1];
        rois     = (const float*)d_in[0];
        rois_elems = in_sizes[0];
    }
    const int N = rois_elems / 6;

    dim3 tgrid(HWSZ / 32, CC / 32, BB);
    dim3 tblk(32, 8);
    nchw_to_nhwc_half_kernel<<<tgrid, tblk>>>(features);

    roi_align_rotated_kernel<<<N * 2, 256>>>(rois, (float*)d_out, N);
}

// round 11
// speedup vs baseline: 1.7286x; 1.0005x over previous
#include <cuda_runtime.h>
#include <cuda_fp16.h>
#include <cuda_bf16.h>
#include <math.h>

// Problem constants (fixed by the dataset)
#define BB 2
#define CC 256
#define HH 200
#define WW 200
#define HWSZ (HH * WW)          // 40000
#define OUT_H 7
#define OUT_W 7
#define GSAMP 2
#define NSAMP (OUT_H * GSAMP * OUT_W * GSAMP)  // 196
#define SPATIAL_SCALE 0.25f
#define NBINS (OUT_H * OUT_W)   // 49
#define HALF_C 128              // channels per CTA
#define RPITCH 132              // 128 + 4 floats per staging row

// NHWC fp16 scratch: 2*200*200*256 halves = 40.96 MB (static device array: allowed)
__device__ __align__(16) __half g_featT[(size_t)BB * HWSZ * CC];

__device__ __forceinline__ __half2 u2h(unsigned int u) {
    __half2 h; *reinterpret_cast<unsigned int*>(&h) = u; return h;
}
__device__ __forceinline__ unsigned int h2u(__half2 h) {
    return *reinterpret_cast<unsigned int*>(&h);
}

// ---------------------------------------------------------------------------
// Kernel 1: NCHW fp32 -> NHWC fp16 transpose (tiled 32x32, coalesced, half2
// vectorized stores). DRAM-bound at ~123MB total traffic.
// ---------------------------------------------------------------------------
__global__ void nchw_to_nhwc_half_kernel(const float* __restrict__ in) {
    __shared__ float tile[32][33];
    const int b  = blockIdx.z;
    const int p0 = blockIdx.x * 32;   // spatial tile origin
    const int c0 = blockIdx.y * 32;   // channel tile origin
    const int tx = threadIdx.x;       // 0..31
    const int ty = threadIdx.y;       // 0..7
    const int tid = ty * 32 + tx;

    const float* src = in + (size_t)b * CC * HWSZ;
    __half* dst = g_featT + (size_t)b * HWSZ * CC;

    #pragma unroll
    for (int i = 0; i < 32; i += 8)
        tile[ty + i][tx] = src[(size_t)(c0 + ty + i) * HWSZ + (p0 + tx)];
    __syncthreads();

    #pragma unroll
    for (int it = 0; it < 2; it++) {
        const int e  = it * 256 + tid;
        const int pl = e >> 4;        // local position 0..31
        const int h  = e & 15;        // half2 index within 32 channels
        const float f0 = tile[2 * h][pl];
        const float f1 = tile[2 * h + 1][pl];
        __half2 v = __floats2half2_rn(f0, f1);
        *reinterpret_cast<__half2*>(dst + (size_t)(p0 + pl) * CC + c0 + 2 * h) = v;
    }
}

// ---------------------------------------------------------------------------
// Kernel 2: RoIAlignRotated gather, fp16 features + half2 bilinear math.
// grid = 2N (channel halves). 256 threads.
// Thread t: oct q = t & 15 (8 local channels), bin group bg = t >> 4.
// Per sample: 4-corner bilinear combo in half2 (HMUL2 + 3x HFMA2 per slot),
// one convert per slot, fp32 accumulation across the 2x2 samples.
// ---------------------------------------------------------------------------
__global__ __launch_bounds__(256, 6)
void roi_align_rotated_kernel(const float* __restrict__ rois,
                              float* __restrict__ out,
                              int N) {
    __shared__ uint4 s_wh[NSAMP];            // 4 duplicated-half2 weights
    __shared__ int4  s_i[NSAMP];             // oct (16B) indices
    __shared__ float s_out[NBINS * RPITCH];  // 25872 B

    const int n    = blockIdx.x >> 1;
    const int half = blockIdx.x & 1;
    const int tid  = threadIdx.x;
    const int q    = tid & 15;                // local oct 0..15
    const int bg   = tid >> 4;                // 0..15

    // --- roi params (broadcast) ---
    const float* R = rois + (size_t)n * 6;
    const int   b     = (int)R[0];
    const float cx    = R[1] * SPATIAL_SCALE;
    const float cy    = R[2] * SPATIAL_SCALE;
    const float rw    = fmaxf(R[3] * SPATIAL_SCALE, 1.0f);
    const float rh    = fmaxf(R[4] * SPATIAL_SCALE, 1.0f);
    const float theta = R[5];
    const float cost  = cosf(theta);
    const float sint  = sinf(theta);
    const float bin_h = rh * (1.0f / OUT_H);
    const float bin_w = rw * (1.0f / OUT_W);

    // --- Phase A: sample-point precompute (reference semantics exactly) ---
    if (tid < NSAMP) {
        const int s = tid;
        const int r = s / (OUT_W * GSAMP);
        const int p = s % (OUT_W * GSAMP);
        const float sy = ((float)r + 0.5f) * (1.0f / GSAMP);
        const float sx = ((float)p + 0.5f) * (1.0f / GSAMP);
        const float yy = -rh * 0.5f + sy * bin_h;
        const float xx = -rw * 0.5f + sx * bin_w;
        const float y = yy * cost - xx * sint + cy;
        const float x = yy * sint + xx * cost + cx;

        const bool inside = (y >= -1.0f) && (y <= (float)HH) &&
                            (x >= -1.0f) && (x <= (float)WW);

        const float yc = fmaxf(y, 0.0f);
        const float xc = fmaxf(x, 0.0f);
        const float fy = floorf(yc);
        const float fx = floorf(xc);
        int yl = min((int)fy, HH - 1);
        int xl = min((int)fx, WW - 1);
        const int yh = min(yl + 1, HH - 1);
        const int xh = min(xl + 1, WW - 1);
        const float ly = (fy >= (float)(HH - 1)) ? 0.0f : (yc - (float)yl);
        const float lx = (fx >= (float)(WW - 1)) ? 0.0f : (xc - (float)xl);
        const float hy = 1.0f - ly;
        const float hx = 1.0f - lx;

        float w1 = hy * hx, w2 = hy * lx, w3 = ly * hx, w4 = ly * lx;
        if (!inside) { w1 = 0.f; w2 = 0.f; w3 = 0.f; w4 = 0.f; }

        uint4 wh;
        wh.x = h2u(__float2half2_rn(w1));   // (w1, w1)
        wh.y = h2u(__float2half2_rn(w2));
        wh.z = h2u(__float2half2_rn(w3));
        wh.w = h2u(__float2half2_rn(w4));

        // index in oct (16B) units: pos * (CC/8) = pos * 32
        const int base = b * HWSZ;
        int4 idx;
        idx.x = (base + yl * WW + xl) * (CC / 8);
        idx.y = (base + yl * WW + xh) * (CC / 8);
        idx.z = (base + yh * WW + xl) * (CC / 8);
        idx.w = (base + yh * WW + xh) * (CC / 8);
        s_i[s]  = idx;
        s_wh[s] = wh;
    }
    __syncthreads();

    // --- Phase B: fp16 oct gather, half2 bilinear, fp32 cross-sample acc ---
    const uint4* __restrict__ ft8 =
        reinterpret_cast<const uint4*>(g_featT) + (half * 16 + q);

    #pragma unroll 1
    for (int j = bg; j < NBINS; j += 16) {
        const int ph = j / OUT_W;
        const int pw = j - ph * OUT_W;
        float acc[8];
        #pragma unroll
        for (int k = 0; k < 8; k++) acc[k] = 0.0f;

        #pragma unroll
        for (int iy = 0; iy < GSAMP; iy++) {
            #pragma unroll
            for (int ix = 0; ix < GSAMP; ix++) {
                const int s = (ph * GSAMP + iy) * (OUT_W * GSAMP)
                            + (pw * GSAMP + ix);
                const int4  ii = s_i[s];    // LDS.128 broadcast
                const uint4 wh = s_wh[s];   // LDS.128 broadcast
                const __half2 w1 = u2h(wh.x);
                const __half2 w2 = u2h(wh.y);
                const __half2 w3 = u2h(wh.z);
                const __half2 w4 = u2h(wh.w);
                const uint4 u1 = __ldg(ft8 + ii.x);
                const uint4 u2 = __ldg(ft8 + ii.y);
                const uint4 u3 = __ldg(ft8 + ii.z);
                const uint4 u4 = __ldg(ft8 + ii.w);
                const __half2* h1 = reinterpret_cast<const __half2*>(&u1);
                const __half2* h2 = reinterpret_cast<const __half2*>(&u2);
                const __half2* h3 = reinterpret_cast<const __half2*>(&u3);
                const __half2* h4 = reinterpret_cast<const __half2*>(&u4);
                #pragma unroll
                for (int k = 0; k < 4; k++) {
                    __half2 t = __hmul2(h1[k], w1);
                    t = __hfma2(h2[k], w2, t);
                    t = __hfma2(h3[k], w3, t);
                    t = __hfma2(h4[k], w4, t);
                    const float2 f = __half22float2(t);
                    acc[2*k]   += f.x;
                    acc[2*k+1] += f.y;
                }
            }
        }
        // mean over 2x2 samples; stage bin-major (two STS.128, conflict-free)
        float4 r0 = make_float4(acc[0] * 0.25f, acc[1] * 0.25f,
                                acc[2] * 0.25f, acc[3] * 0.25f);
        float4 r1 = make_float4(acc[4] * 0.25f, acc[5] * 0.25f,
                                acc[6] * 0.25f, acc[7] * 0.25f);
        float* row = &s_out[j * RPITCH + 8 * q];
        *reinterpret_cast<float4*>(row)     = r0;
        *reinterpret_cast<float4*>(row + 4) = r1;
    }
    __syncthreads();

    // --- Phase C: coalesced contiguous store of this half's output slab ---
    float* outp = out + (size_t)n * (CC * NBINS) + (size_t)half * (HALF_C * NBINS);
    #pragma unroll 1
    for (int i = tid; i < HALF_C * NBINS; i += 256) {
        const int c = i / NBINS;      // local channel 0..127
        const int j = i - c * NBINS;  // bin 0..48
        outp[i] = s_out[j * RPITCH + c];
    }
}

// ---------------------------------------------------------------------------
extern "C" void kernel_launch(void* const* d_in, const int* in_sizes, int n_in,
                              void* d_out, int out_size) {
    const float* features;
    const float* rois;
    int rois_elems;
    if (in_sizes[0] > in_sizes[1]) {
        features = (const float*)d_in[0];
        rois     = (const float*)d_in[1];
        rois_elems = in_sizes[1];
    } else {
        features = (const float*)d_in[1];
        rois     = (const float*)d_in[0];
        rois_elems = in_sizes[0];
    }
    const int N = rois_elems / 6;

    dim3 tgrid(HWSZ / 32, CC / 32, BB);
    dim3 tblk(32, 8);
    nchw_to_nhwc_half_kernel<<<tgrid, tblk>>>(features);

    roi_align_rotated_kernel<<<N * 2, 256>>>(rois, (float*)d_out, N);
}